// round 1
// baseline (speedup 1.0000x reference)
#include <cuda_runtime.h>
#include <cfloat>
#include <cstdint>

// Problem shape (fixed by the dataset)
#define BB 8
#define CC 3
#define HH 1080
#define WW 1920
#define KK 256
#define NBASIS 25
#define GBINS 4096          // power of two: x*4096.0f is EXACT in fp32
#define NSEG (KK + 1)       // 257 extended segments: flat-left, K-1 interior, flat-right
#define PIX_PER_BATCH (CC * HH * WW)   // 6,220,800 (divisible by 4)

// Per-batch tables (device globals: no allocation allowed)
__device__ float2 gBins[BB * GBINS];   // (a,b) pure bins, or NaN-payload(k0) kinked bins
__device__ float4 gSegs[BB * NSEG];    // (Elo, Ehi, a, b) exact segments

// ---------------------------------------------------------------------------
// Precompute kernel: one block per batch.
//   curve[k] = f0[k] + sum_n H[k,n] * w[b,n]
//   segments: seg[0]=(-inf,E0,0,c0), seg[k]=(E[k-1],E[k],a,b), seg[K]=(E[K-1],+inf,0,cK-1)
//   bins: pure if [g/4096,(g+1)/4096) within one segment -> (a,b); else NaN|k0
// ---------------------------------------------------------------------------
__global__ void tmo_precompute(const float* __restrict__ w,
                               const float* __restrict__ E,
                               const float* __restrict__ f0,
                               const float* __restrict__ Hb) {
    __shared__ float sE[KK];
    __shared__ float sC[KK];
    const int b = blockIdx.x;
    const int t = threadIdx.x;

    if (t < KK) {
        float e = E[t];
        float acc = f0[t];
        #pragma unroll
        for (int n = 0; n < NBASIS; n++)
            acc = fmaf(Hb[t * NBASIS + n], w[b * NBASIS + n], acc);
        sE[t] = e;
        sC[t] = acc;
    }
    __syncthreads();

    // Build segment table
    for (int k = t; k < NSEG; k += blockDim.x) {
        float4 s;
        if (k == 0) {
            s = make_float4(-FLT_MAX, sE[0], 0.0f, sC[0]);
        } else if (k == KK) {
            s = make_float4(sE[KK - 1], FLT_MAX, 0.0f, sC[KK - 1]);
        } else {
            float a = (sC[k] - sC[k - 1]) / (sE[k] - sE[k - 1]);
            s = make_float4(sE[k - 1], sE[k], a, fmaf(-a, sE[k - 1], sC[k - 1]));
        }
        gSegs[b * NSEG + k] = s;
    }

    // Build bin table
    for (int g = t; g < GBINS; g += blockDim.x) {
        float left  = (float)g       * (1.0f / GBINS);  // exact (g * 2^-12)
        float right = (float)(g + 1) * (1.0f / GBINS);  // exact
        // k0 = count of E values <= left  (segment index in extended table)
        int lo = 0, hi = KK;
        while (lo < hi) {
            int mid = (lo + hi) >> 1;
            if (sE[mid] <= left) lo = mid + 1; else hi = mid;
        }
        int k0 = lo;
        float upper = (k0 < KK) ? sE[k0] : FLT_MAX;
        float2 ab;
        if (upper >= right) {
            // entire bin inside segment k0
            if (k0 == 0) {
                ab = make_float2(0.0f, sC[0]);
            } else if (k0 == KK) {
                ab = make_float2(0.0f, sC[KK - 1]);
            } else {
                float a = (sC[k0] - sC[k0 - 1]) / (sE[k0] - sE[k0 - 1]);
                ab = make_float2(a, fmaf(-a, sE[k0 - 1], sC[k0 - 1]));
            }
        } else {
            // kinked bin: quiet-NaN with segment-start payload
            ab = make_float2(__int_as_float(0x7FC00000 | k0), 0.0f);
        }
        gBins[b * GBINS + g] = ab;
    }
}

// ---------------------------------------------------------------------------
// Main kernel: grid (blocks_x, B). Each block serves one batch, loads that
// batch's tables into shared, then streams pixels as float4.
// ---------------------------------------------------------------------------
__global__ void __launch_bounds__(256, 6)
tmo_apply(const float* __restrict__ img, float* __restrict__ out) {
    __shared__ float2 sBins[GBINS];   // 32 KB
    __shared__ float4 sSegs[NSEG];    // ~4.1 KB

    const int b = blockIdx.y;

    // Cooperative table load (vectorized)
    {
        const float4* src = reinterpret_cast<const float4*>(gBins + (size_t)b * GBINS);
        float4* dst = reinterpret_cast<float4*>(sBins);
        for (int i = threadIdx.x; i < GBINS / 2; i += blockDim.x) dst[i] = src[i];
        for (int i = threadIdx.x; i < NSEG; i += blockDim.x)
            sSegs[i] = gSegs[b * NSEG + i];
    }
    __syncthreads();

    const float4* in4  = reinterpret_cast<const float4*>(img + (size_t)b * PIX_PER_BATCH);
    float4*       out4 = reinterpret_cast<float4*>(out + (size_t)b * PIX_PER_BATCH);
    const int nF4 = PIX_PER_BATCH / 4;
    const int stride = gridDim.x * blockDim.x;

    for (int i = blockIdx.x * blockDim.x + threadIdx.x; i < nF4; i += stride) {
        float4 v = in4[i];
        float r[4] = {v.x, v.y, v.z, v.w};
        #pragma unroll
        for (int j = 0; j < 4; j++) {
            float x = r[j];
            float xg = x * (float)GBINS;           // exact: multiply by 2^12
            int g = (int)xg;
            g = min(max(g, 0), GBINS - 1);
            float2 ab = sBins[g];
            float y;
            if (!__isnanf(ab.x)) {
                y = fmaf(ab.x, x, ab.y);
            } else {
                int k = __float_as_int(ab.x) & 0xFFFF;
                float4 s = sSegs[k];
                while (x >= s.y) { k++; s = sSegs[k]; }
                y = fmaf(s.z, x, s.w);
            }
            r[j] = fminf(fmaxf(y, 0.0f), 1.0f);
        }
        out4[i] = make_float4(r[0], r[1], r[2], r[3]);
    }
}

extern "C" void kernel_launch(void* const* d_in, const int* in_sizes, int n_in,
                              void* d_out, int out_size) {
    const float* hdr = (const float*)d_in[0];   // [B,C,H,W]
    const float* w   = (const float*)d_in[1];   // [B,NB]
    const float* E   = (const float*)d_in[2];   // [K]
    const float* f0  = (const float*)d_in[3];   // [K]
    const float* Hb  = (const float*)d_in[4];   // [K,NB]
    float* out = (float*)d_out;

    tmo_precompute<<<BB, 256>>>(w, E, f0, Hb);

    dim3 grid(96, BB);   // 768 blocks = one full wave at 6 CTAs/SM
    tmo_apply<<<grid, 256>>>(hdr, out);
}